// round 3
// baseline (speedup 1.0000x reference)
#include <cuda_runtime.h>
#include <cstdint>

// Problem constants
#define NB       128
#define C_DIM    64
#define HW_DIM   3136
#define M_DIM    6
#define D_DIM    192
#define INNER    512
#define NROWS    48      // heads*M
#define TN       64      // n-tile
#define NT       49      // HW/TN (exact)
#define NTHREADS 256

typedef unsigned long long u64;

// ---- packed f32x2 helpers (sm_100+) ----
__device__ __forceinline__ u64 ffma2(u64 a, u64 b, u64 c){
    u64 d; asm("fma.rn.f32x2 %0, %1, %2, %3;" : "=l"(d) : "l"(a), "l"(b), "l"(c)); return d;
}
__device__ __forceinline__ u64 fadd2(u64 a, u64 b){
    u64 d; asm("add.rn.f32x2 %0, %1, %2;" : "=l"(d) : "l"(a), "l"(b)); return d;
}
__device__ __forceinline__ u64 pack2(float x, float y){
    u64 d; asm("mov.b64 %0, {%1, %2};" : "=l"(d) : "f"(x), "f"(y)); return d;
}
__device__ __forceinline__ float2 unpack2(u64 a){
    float2 f; asm("mov.b64 {%0, %1}, %2;" : "=f"(f.x), "=f"(f.y) : "l"(a)); return f;
}

// shared memory layout (float offsets). q2/p2 rows padded to 66 u64 to kill
// cross-ty-group bank aliasing; xnc uses an XOR-4 swizzle at stride 64.
#define Q2_OFF    0                       // u64 [48][66]  = 6336 floats
#define XCN_OFF   6336                    // float [2][64][64]
#define XNC_OFF   (6336 + 8192)           // float [2][64][64] (swizzled)
#define P2_OFF    (6336 + 8192 + 8192)    // u64 [48][66]  = 6336 floats
#define SMEM_FLOATS (6336 + 8192 + 8192 + 6336)   // 29056 floats = 116224 B

__global__ void __launch_bounds__(NTHREADS, 1)
m2f_kernel(const float* __restrict__ x, const float* __restrict__ z,
           const float* __restrict__ Wq, const float* __restrict__ bq,
           const float* __restrict__ Wo, const float* __restrict__ bo,
           float* __restrict__ out)
{
    extern __shared__ float sm[];
    u64*   q2  = (u64*)sm;                 // [48][66] duplicated-pair scaled q
    float* xcn = sm + XCN_OFF;             // c-major x tile, double buffered
    float* xnc = sm + XNC_OFF;             // n-major x tile (swizzled), double buffered
    u64*   p2  = (u64*)(sm + P2_OFF);      // [48][66] duplicated-pair exp(S)

    const int b   = blockIdx.x;
    const int tid = threadIdx.x;
    const int ty  = tid >> 4;              // 0..15
    const int tx  = tid & 15;              // 0..15
    const int r0  = ty * 3;                // 3 rows per thread (48 rows)
    const int c0  = tx * 4;                // 4 cols per thread (64 cols)

    // ---------------- stage z (into xcn area, freed before tiles) ----------------
    float* zs = xcn;
    {
        const float* zb = z + (size_t)b * (M_DIM * D_DIM);
        for (int i = tid; i < M_DIM * D_DIM; i += NTHREADS) zs[i] = zb[i];
    }
    __syncthreads();

    // ---------------- q projection: qflat[3072] = z[b] @ Wq + bq, * C^-0.5 ------
    {
        const int j0 = tid * 2;            // 256 threads x 2 cols = 512
        float ax[M_DIM], ay[M_DIM];
        const float b0 = bq[j0], b1 = bq[j0 + 1];
        #pragma unroll
        for (int m = 0; m < M_DIM; m++){ ax[m] = b0; ay[m] = b1; }
        #pragma unroll 4
        for (int k = 0; k < D_DIM; k++){
            float2 w = *(const float2*)(Wq + (size_t)k * INNER + j0);
            #pragma unroll
            for (int m = 0; m < M_DIM; m++){
                float zv = zs[m * D_DIM + k];
                ax[m] = fmaf(zv, w.x, ax[m]);
                ay[m] = fmaf(zv, w.y, ay[m]);
            }
        }
        const float scale = 0.125f;        // 64^-0.5 folded into q
        #pragma unroll
        for (int m = 0; m < M_DIM; m++){
            int f0 = m * INNER + j0;       // flat [6,512] == flat [48,64]
            int r_ = f0 >> 6, c_ = f0 & 63;
            float qa = ax[m] * scale, qb = ay[m] * scale;
            q2[r_ * 66 + c_]     = pack2(qa, qa);
            q2[r_ * 66 + c_ + 1] = pack2(qb, qb);
        }
    }
    __syncthreads();   // q2 ready; zs dead -> xcn reusable

    // ---------------- main fused attention loop --------------------------------
    const float* xb = x + (size_t)b * C_DIM * HW_DIM;
    float4 pref[4];

    // prefetch tile 0 (slot s = tid + 256p -> c = s>>4, n-group g = s&15)
    #pragma unroll
    for (int p = 0; p < 4; p++){
        int s = tid + NTHREADS * p;
        int cc = s >> 4, g = s & 15;
        pref[p] = *(const float4*)(xb + (size_t)cc * HW_DIM + 4 * g);
    }

    auto store_tile = [&](int buf){
        float* xc = xcn + buf * (C_DIM * TN);
        float* xn = xnc + buf * (TN * C_DIM);
        #pragma unroll
        for (int p = 0; p < 4; p++){
            int s = tid + NTHREADS * p;
            int cc = s >> 4, g = s & 15;
            *(float4*)(xc + cc * TN + 4 * g) = pref[p];
            float v[4] = {pref[p].x, pref[p].y, pref[p].z, pref[p].w};
            #pragma unroll
            for (int kk = 0; kk < 4; kk++){
                int n = 4 * g + kk;
                int csw = ((cc & ~3) ^ ((n & 15) << 2)) | (cc & 3);  // XOR-4 swizzle
                xn[n * 64 + csw] = v[kk];
            }
        }
    };

    u64 oacc[3][2], rsum[3];
    #pragma unroll
    for (int i = 0; i < 3; i++){ oacc[i][0] = 0ULL; oacc[i][1] = 0ULL; rsum[i] = 0ULL; }

    store_tile(0);
    __syncthreads();

    const u64* q2r = q2 + r0 * 66;
    u64*       p2r = p2 + r0 * 66;

    for (int t = 0; t < NT; t++){
        const int cur = t & 1;
        const float* xcn_c = xcn + cur * (C_DIM * TN);
        const float* xnc_c = xnc + cur * (TN * C_DIM);

        // prefetch next tile into registers (overlaps GEMM1)
        if (t + 1 < NT){
            int n0 = (t + 1) * TN;
            #pragma unroll
            for (int p = 0; p < 4; p++){
                int s = tid + NTHREADS * p;
                int cc = s >> 4, g = s & 15;
                pref[p] = *(const float4*)(xb + (size_t)cc * HW_DIM + n0 + 4 * g);
            }
        }

        // GEMM1: S[3][4] = q[3rows] . xtile  (k over C=64)
        u64 s2[3][2];
        #pragma unroll
        for (int i = 0; i < 3; i++){ s2[i][0] = 0ULL; s2[i][1] = 0ULL; }
        #pragma unroll 16
        for (int k = 0; k < C_DIM; k++){
            const u64* xv = (const u64*)(xcn_c + k * TN + c0);
            u64 xlo = xv[0], xhi = xv[1];
            #pragma unroll
            for (int i = 0; i < 3; i++){
                u64 qd = q2r[i * 66 + k];
                s2[i][0] = ffma2(qd, xlo, s2[i][0]);
                s2[i][1] = ffma2(qd, xhi, s2[i][1]);
            }
        }

        // exp (no max needed: |logit| <~ 2), rowsum, stage duplicated P pairs
        #pragma unroll
        for (int i = 0; i < 3; i++){
            float2 a  = unpack2(s2[i][0]);
            float2 bb = unpack2(s2[i][1]);
            float e0 = __expf(a.x),  e1 = __expf(a.y);
            float e2 = __expf(bb.x), e3 = __expf(bb.y);
            rsum[i] = fadd2(rsum[i], pack2(e0 + e2, e1 + e3));
            u64* dst = p2r + i * 66 + c0;
            ulonglong2 st0; st0.x = pack2(e0, e0); st0.y = pack2(e1, e1);
            ulonglong2 st1; st1.x = pack2(e2, e2); st1.y = pack2(e3, e3);
            *(ulonglong2*)(dst)     = st0;
            *(ulonglong2*)(dst + 2) = st1;
        }
        __syncthreads();             // P visible to all before GEMM2

        if (t + 1 < NT) store_tile((t + 1) & 1);

        // GEMM2: O[3][4cols of C] += P[3rows] . x^T  (k over n=64)
        #pragma unroll 16
        for (int n = 0; n < TN; n++){
            const u64* xv = (const u64*)(xnc_c + n * 64 + (c0 ^ ((n & 15) << 2)));
            u64 xlo = xv[0], xhi = xv[1];
            #pragma unroll
            for (int i = 0; i < 3; i++){
                u64 pd = p2r[i * 66 + n];
                oacc[i][0] = ffma2(pd, xlo, oacc[i][0]);
                oacc[i][1] = ffma2(pd, xhi, oacc[i][1]);
            }
        }
        __syncthreads();             // P/xtile fully consumed before next overwrite
    }

    // ---------------- normalize: rowsum reduce over the 16 tx lanes -------------
    float inv[3];
    #pragma unroll
    for (int i = 0; i < 3; i++){
        float2 rr = unpack2(rsum[i]);
        float l = rr.x + rr.y;
        #pragma unroll
        for (int mm = 1; mm <= 8; mm <<= 1)
            l += __shfl_xor_sync(0xffffffffu, l, mm);
        inv[i] = 1.0f / l;
    }

    // ---------------- stage res (transposed to [hc=512][m-pairs]) ---------------
    __syncthreads();
    float* resm = sm;                      // [512][8] overlay (16 KB, q2 dead)
    #pragma unroll
    for (int i = 0; i < 3; i++){
        int r = r0 + i;
        int h = r / 6, m = r - 6 * h;      // out col = h*64 + c, out row = m
        float2 v0 = unpack2(oacc[i][0]);
        float2 v1 = unpack2(oacc[i][1]);
        float vv[4] = {v0.x, v0.y, v1.x, v1.y};
        #pragma unroll
        for (int j2 = 0; j2 < 4; j2++){
            int hc = h * 64 + c0 + j2;
            resm[hc * 8 + m] = vv[j2] * inv[i];
        }
    }
    __syncthreads();

    // ---------------- out = resT @ Wo + bo + z ----------------------------------
    if (tid < D_DIM){
        const int j = tid;
        u64 acc[3] = {0ULL, 0ULL, 0ULL};
        #pragma unroll 8
        for (int k = 0; k < INNER; k++){
            float w = Wo[(size_t)k * D_DIM + j];
            u64 wd = pack2(w, w);
            const u64* rm = (const u64*)(resm + k * 8);
            #pragma unroll
            for (int p = 0; p < 3; p++)
                acc[p] = ffma2(wd, rm[p], acc[p]);
        }
        const float bj = bo[j];
        const float* zb = z   + (size_t)b * M_DIM * D_DIM;
        float*       ob = out + (size_t)b * M_DIM * D_DIM;
        #pragma unroll
        for (int p = 0; p < 3; p++){
            float2 v = unpack2(acc[p]);
            ob[(2 * p)     * D_DIM + j] = v.x + bj + zb[(2 * p)     * D_DIM + j];
            ob[(2 * p + 1) * D_DIM + j] = v.y + bj + zb[(2 * p + 1) * D_DIM + j];
        }
    }
}

extern "C" void kernel_launch(void* const* d_in, const int* in_sizes, int n_in,
                              void* d_out, int out_size)
{
    const float* x  = (const float*)d_in[0];
    const float* z  = (const float*)d_in[1];
    const float* Wq = (const float*)d_in[2];
    const float* bq = (const float*)d_in[3];
    const float* Wo = (const float*)d_in[4];
    const float* bo = (const float*)d_in[5];
    float* out = (float*)d_out;

    // idempotent, not a stream op — safe under graph capture
    cudaFuncSetAttribute(m2f_kernel, cudaFuncAttributeMaxDynamicSharedMemorySize,
                         SMEM_FLOATS * sizeof(float));
    m2f_kernel<<<NB, NTHREADS, SMEM_FLOATS * sizeof(float)>>>(x, z, Wq, bq, Wo, bo, out);
}

// round 6
// speedup vs baseline: 2.8020x; 2.8020x over previous
#include <cuda_runtime.h>
#include <cstdint>

typedef unsigned int u32;
typedef unsigned long long u64;

#define HW_DIM   3136
#define M_DIM    6
#define D_DIM    192
#define INNER    512
#define NT       49
#define NTHREADS 256
#define NB       128

// ---- SMEM byte map ----
#define SM_REX   0                 // 128 floats rowsum exchange (512B)
#define SM_P     512               // P tile bf16 [64][64]  (8192B)
#define SM_X     8704              // X tiles bf16, 2 x [64][64] (2 x 8192B)
#define SM_ZS    25088             // staged z (1152 floats = 4608B)
#define SM_QS    29696             // q f32 [64][64] (16384B)
#define SM_RESM  46080             // res staged [512][8] f32 (16384B)
#define SM_TOTAL 62464

// ================= helpers =================
__device__ __forceinline__ u32 smem_u32(const void* p){
    u32 a; asm("{ .reg .u64 t; cvta.to.shared.u64 t, %1; cvt.u32.u64 %0, t; }" : "=r"(a) : "l"(p)); return a;
}
__device__ __forceinline__ u32 sw(u32 o){ return o ^ ((o >> 3) & 0x70); }

__device__ __forceinline__ float ex2f(float x){
    float y; asm("ex2.approx.ftz.f32 %0, %1;" : "=f"(y) : "f"(x)); return y;
}
__device__ __forceinline__ u32 bf16x2(float hi, float lo){
    u32 d; asm("cvt.rn.bf16x2.f32 %0, %1, %2;" : "=r"(d) : "f"(hi), "f"(lo)); return d;
}
__device__ __forceinline__ void ldsm4(u32& r0, u32& r1, u32& r2, u32& r3, u32 a){
    asm volatile("ldmatrix.sync.aligned.m8n8.x4.shared.b16 {%0,%1,%2,%3}, [%4];"
        : "=r"(r0), "=r"(r1), "=r"(r2), "=r"(r3) : "r"(a));
}
__device__ __forceinline__ void ldsm4t(u32& r0, u32& r1, u32& r2, u32& r3, u32 a){
    asm volatile("ldmatrix.sync.aligned.m8n8.x4.trans.shared.b16 {%0,%1,%2,%3}, [%4];"
        : "=r"(r0), "=r"(r1), "=r"(r2), "=r"(r3) : "r"(a));
}
__device__ __forceinline__ void mma_bf16(float* d, const u32* a, u32 b0, u32 b1){
    asm volatile("mma.sync.aligned.m16n8k16.row.col.f32.bf16.bf16.f32 "
        "{%0,%1,%2,%3}, {%4,%5,%6,%7}, {%8,%9}, {%0,%1,%2,%3};"
        : "+f"(d[0]), "+f"(d[1]), "+f"(d[2]), "+f"(d[3])
        : "r"(a[0]), "r"(a[1]), "r"(a[2]), "r"(a[3]), "r"(b0), "r"(b1));
}
// ---- packed f32x2 ----
__device__ __forceinline__ u64 ffma2(u64 a, u64 b, u64 c){
    u64 d; asm("fma.rn.f32x2 %0, %1, %2, %3;" : "=l"(d) : "l"(a), "l"(b), "l"(c)); return d;
}
__device__ __forceinline__ u64 pack2(float x, float y){
    u64 d; asm("mov.b64 %0, {%1, %2};" : "=l"(d) : "f"(x), "f"(y)); return d;
}
__device__ __forceinline__ float2 unpack2(u64 a){
    float2 f; asm("mov.b64 {%0, %1}, %2;" : "=f"(f.x), "=f"(f.y) : "l"(a)); return f;
}

__global__ void __launch_bounds__(NTHREADS, 1)
m2f_mma_kernel(const float* __restrict__ x, const float* __restrict__ z,
               const float* __restrict__ Wq, const float* __restrict__ bq,
               const float* __restrict__ Wo, const float* __restrict__ bo,
               float* __restrict__ out)
{
    extern __shared__ char sm[];
    float* sm_f = (float*)sm;

    const int b    = blockIdx.x;
    const int tid  = threadIdx.x;
    const int wid  = tid >> 5;
    const int lane = tid & 31;
    const int mt   = wid & 3;          // m-tile (16 q-rows)
    const int nh   = wid >> 2;         // n-half (32 cols)
    const u32 smb  = smem_u32(sm);

    const float* xb = x + (size_t)b * 64 * HW_DIM;

    // ---------------- stage z ---------------------------------------------------
    float* zs = sm_f + SM_ZS / 4;
    {
        const float* zb = z + (size_t)b * (M_DIM * D_DIM);
        for (int i = tid; i < M_DIM * D_DIM; i += NTHREADS) zs[i] = zb[i];
    }
    __syncthreads();

    // ---------------- q projection -> qs[64][64] f32 (rows 48-63 zero) -----------
    float* qs = sm_f + SM_QS / 4;
    {
        const int j0 = tid * 2;
        float ax[M_DIM], ay[M_DIM];
        const float b0 = bq[j0], b1 = bq[j0 + 1];
        #pragma unroll
        for (int m = 0; m < M_DIM; m++){ ax[m] = b0; ay[m] = b1; }
        #pragma unroll 4
        for (int k = 0; k < D_DIM; k++){
            float2 w = *(const float2*)(Wq + (size_t)k * INNER + j0);
            #pragma unroll
            for (int m = 0; m < M_DIM; m++){
                float zv = zs[m * D_DIM + k];
                ax[m] = fmaf(zv, w.x, ax[m]);
                ay[m] = fmaf(zv, w.y, ay[m]);
            }
        }
        const float scale = 0.18033688011112042f;   // 64^-0.5 * log2(e) -> ex2 softmax
        #pragma unroll
        for (int m = 0; m < M_DIM; m++){
            int f0 = m * INNER + j0;                // flat [6,512] == flat [48,64]
            int r_ = f0 >> 6, c_ = f0 & 63;
            qs[r_ * 64 + c_]     = ax[m] * scale;
            qs[r_ * 64 + c_ + 1] = ay[m] * scale;
        }
        for (int i = tid; i < 16 * 64; i += NTHREADS) qs[48 * 64 + i] = 0.f;
    }
    __syncthreads();

    // ---------------- Q -> persistent bf16 A fragments ---------------------------
    // a-frag reg: 0:(r, c..c+1) 1:(r+8, c) 2:(r, c+8) 3:(r+8, c+8)
    u32 aq[4][4];
    {
        int r  = 16 * mt + (lane >> 2);
        int c  = (lane & 3) * 2;
        #pragma unroll
        for (int ks = 0; ks < 4; ks++){
            float2 v0 = *(const float2*)(qs + r * 64        + 16 * ks + c);
            float2 v1 = *(const float2*)(qs + (r + 8) * 64  + 16 * ks + c);
            float2 v2 = *(const float2*)(qs + r * 64        + 16 * ks + c + 8);
            float2 v3 = *(const float2*)(qs + (r + 8) * 64  + 16 * ks + c + 8);
            aq[ks][0] = bf16x2(v0.y, v0.x);
            aq[ks][1] = bf16x2(v1.y, v1.x);
            aq[ks][2] = bf16x2(v2.y, v2.x);
            aq[ks][3] = bf16x2(v3.y, v3.x);
        }
    }

    // ---------------- X tile load helpers ---------------------------------------
    // thread t: row cc = t>>2 (0-63), group ng = t&3 (16 f32 -> 16 bf16 = 32B)
    const int cc = tid >> 2, ng = tid & 3;
    const float* xrow = xb + (size_t)cc * HW_DIM + ng * 16;
    float4 v[4];

    auto ldg_tile = [&](int t){
        const float* src = xrow + 64 * t;
        #pragma unroll
        for (int i = 0; i < 4; i++) v[i] = *(const float4*)(src + 4 * i);
    };
    auto sts_tile = [&](int buf){
        char* dst = sm + SM_X + buf * 8192;
        uint4 p0, p1;
        p0.x = bf16x2(v[0].y, v[0].x); p0.y = bf16x2(v[0].w, v[0].z);
        p0.z = bf16x2(v[1].y, v[1].x); p0.w = bf16x2(v[1].w, v[1].z);
        p1.x = bf16x2(v[2].y, v[2].x); p1.y = bf16x2(v[2].w, v[2].z);
        p1.z = bf16x2(v[3].y, v[3].x); p1.w = bf16x2(v[3].w, v[3].z);
        u32 base = (u32)(cc * 128 + ng * 32);
        *(uint4*)(dst + sw(base))      = p0;
        *(uint4*)(dst + sw(base + 16)) = p1;
    };

    ldg_tile(0); sts_tile(0);
    ldg_tile(1);
    __syncthreads();

    // ---------------- per-thread invariant ldmatrix address parts ----------------
    const u32 smP = smb + SM_P;
    const int lrow = ((lane >> 3) & 1) * 8 + (lane & 7);
    // GEMM1 B (trans): row = 16ks + lrow ; chunk = 4nh + 2np + (lane>>4)
    const u32 g1chunk = (u32)(4 * nh + (lane >> 4));
    // GEMM2 A: row = 16mt + lrow ; chunk = 2ks + (lane>>4)
    const u32 g2arow  = (u32)(16 * mt + lrow);
    // GEMM2 B: row = 32nh + 16cp + (lane>>4)*8 + (lane&7) ; chunk = 2ks + ((lane>>3)&1)
    const u32 g2brow  = (u32)(32 * nh + (lane >> 4) * 8 + (lane & 7));
    const u32 g2bch   = (u32)((lane >> 3) & 1);

    const int rA = 16 * mt + (lane >> 2);
    const int rB = rA + 8;
    const int cB = 32 * nh + (lane & 3) * 2;

    float o[4][4];
    #pragma unroll
    for (int i = 0; i < 4; i++)
        #pragma unroll
        for (int j = 0; j < 4; j++) o[i][j] = 0.f;
    float racc0 = 0.f, racc1 = 0.f;

    // ---------------- main loop --------------------------------------------------
    for (int t = 0; t < NT; t++){
        const u32 XS = smb + SM_X + (u32)(t & 1) * 8192;

        // GEMM1: S = Q . Xtile   (k = c)
        float s[4][4];
        #pragma unroll
        for (int i = 0; i < 4; i++)
            #pragma unroll
            for (int j = 0; j < 4; j++) s[i][j] = 0.f;
        #pragma unroll
        for (int ks = 0; ks < 4; ks++){
            #pragma unroll
            for (int np = 0; np < 2; np++){
                u32 b0, b1, b2, b3;
                u32 ad = XS + sw((u32)((16 * ks + lrow) * 128) + (g1chunk + 2 * np) * 16);
                ldsm4t(b0, b1, b2, b3, ad);
                mma_bf16(s[2 * np],     aq[ks], b0, b1);
                mma_bf16(s[2 * np + 1], aq[ks], b2, b3);
            }
        }

        // exp + rowsum + pack P to smem bf16
        #pragma unroll
        for (int nt = 0; nt < 4; nt++){
            float e0 = ex2f(s[nt][0]), e1 = ex2f(s[nt][1]);
            float e2 = ex2f(s[nt][2]), e3 = ex2f(s[nt][3]);
            racc0 += e0 + e1;
            racc1 += e2 + e3;
            u32 colb = (u32)((cB + 8 * nt) * 2);
            *(u32*)(sm + SM_P + sw((u32)(rA * 128) + colb)) = bf16x2(e1, e0);
            *(u32*)(sm + SM_P + sw((u32)(rB * 128) + colb)) = bf16x2(e3, e2);
        }
        __syncthreads();   // P complete

        // GEMM2: O += P . X^T   (k = n)
        #pragma unroll
        for (int ks = 0; ks < 4; ks++){
            u32 a0, a1, a2, a3;
            u32 ad = smP + sw(g2arow * 128 + (u32)(2 * ks + (lane >> 4)) * 16);
            ldsm4(a0, a1, a2, a3, ad);
            u32 ap[4] = {a0, a1, a2, a3};
            #pragma unroll
            for (int cp = 0; cp < 2; cp++){
                u32 b0, b1, b2, b3;
                u32 bd = XS + sw((g2brow + 16 * cp) * 128 + (u32)(2 * ks) * 16 + g2bch * 16);
                ldsm4(b0, b1, b2, b3, bd);
                mma_bf16(o[2 * cp],     ap, b0, b1);
                mma_bf16(o[2 * cp + 1], ap, b2, b3);
            }
        }

        // stage next tiles
        if (t + 1 < NT) sts_tile((t + 1) & 1);
        if (t + 2 < NT) ldg_tile(t + 2);
        __syncthreads();   // next X ready; P consumed
    }

    // ---------------- rowsum reduce ---------------------------------------------
    racc0 += __shfl_xor_sync(0xffffffffu, racc0, 1);
    racc0 += __shfl_xor_sync(0xffffffffu, racc0, 2);
    racc1 += __shfl_xor_sync(0xffffffffu, racc1, 1);
    racc1 += __shfl_xor_sync(0xffffffffu, racc1, 2);
    float* rex = sm_f + SM_REX / 4;
    if ((lane & 3) == 0){
        rex[wid * 16 + (lane >> 2)]     = racc0;
        rex[wid * 16 + (lane >> 2) + 8] = racc1;
    }
    __syncthreads();

    // ---------------- normalize + stage res [hc=512][m-pairs(8)] -----------------
    float* resm = sm_f + SM_RESM / 4;
    {
        float invA = 0.f, invB = 0.f;
        if (rA < 48) invA = 1.0f / (rex[mt * 16 + (lane >> 2)]     + rex[(mt + 4) * 16 + (lane >> 2)]);
        if (rB < 48) invB = 1.0f / (rex[mt * 16 + (lane >> 2) + 8] + rex[(mt + 4) * 16 + (lane >> 2) + 8]);
        int hA = rA / 6, mA = rA - 6 * hA;
        int hB = rB / 6, mB = rB - 6 * hB;
        #pragma unroll
        for (int nt = 0; nt < 4; nt++){
            int c = cB + 8 * nt;
            if (rA < 48){
                resm[(hA * 64 + c)     * 8 + mA] = o[nt][0] * invA;
                resm[(hA * 64 + c + 1) * 8 + mA] = o[nt][1] * invA;
            }
            if (rB < 48){
                resm[(hB * 64 + c)     * 8 + mB] = o[nt][2] * invB;
                resm[(hB * 64 + c + 1) * 8 + mB] = o[nt][3] * invB;
            }
        }
    }
    __syncthreads();

    // ---------------- out = resT @ Wo + bo + z ----------------------------------
    if (tid < D_DIM){
        const int j = tid;
        u64 acc[3] = {0ULL, 0ULL, 0ULL};
        #pragma unroll 8
        for (int k = 0; k < INNER; k++){
            float w = Wo[(size_t)k * D_DIM + j];
            u64 wd = pack2(w, w);
            const u64* rm = (const u64*)(resm + k * 8);
            #pragma unroll
            for (int p = 0; p < 3; p++)
                acc[p] = ffma2(wd, rm[p], acc[p]);
        }
        const float bj = bo[j];
        const float* zb = z   + (size_t)b * M_DIM * D_DIM;
        float*       ob = out + (size_t)b * M_DIM * D_DIM;
        #pragma unroll
        for (int p = 0; p < 3; p++){
            float2 vv = unpack2(acc[p]);
            ob[(2 * p)     * D_DIM + j] = vv.x + bj + zb[(2 * p)     * D_DIM + j];
            ob[(2 * p + 1) * D_DIM + j] = vv.y + bj + zb[(2 * p + 1) * D_DIM + j];
        }
    }
}

extern "C" void kernel_launch(void* const* d_in, const int* in_sizes, int n_in,
                              void* d_out, int out_size)
{
    const float* x  = (const float*)d_in[0];
    const float* z  = (const float*)d_in[1];
    const float* Wq = (const float*)d_in[2];
    const float* bq = (const float*)d_in[3];
    const float* Wo = (const float*)d_in[4];
    const float* bo = (const float*)d_in[5];
    float* out = (float*)d_out;

    cudaFuncSetAttribute(m2f_mma_kernel, cudaFuncAttributeMaxDynamicSharedMemorySize, SM_TOTAL);
    m2f_mma_kernel<<<NB, NTHREADS, SM_TOTAL>>>(x, z, Wq, bq, Wo, bo, out);
}

// round 7
// speedup vs baseline: 3.2514x; 1.1604x over previous
#include <cuda_runtime.h>
#include <cstdint>

typedef unsigned int u32;
typedef unsigned long long u64;

#define HW_DIM   3136
#define M_DIM    6
#define D_DIM    192
#define INNER    512
#define NT       49
#define NTHREADS 256
#define NB       128

// ---- SMEM byte map ----
#define SM_REX   0                 // 128 floats rowsum exchange (512B)
#define SM_P     512               // P tile bf16 [64][64]  (8192B)
#define SM_X     8704              // X tiles bf16, 2 x [64][64] (2 x 8192B)
#define SM_ZS    25088             // staged z (1152 floats = 4608B); later: combine flag
#define SM_QS    29696             // q f32 [64][64] (16384B)
#define SM_RESM  46080             // res staged [512][8] f32 (16384B)
#define SM_TOTAL 62464

// ---- split-HW partial scratch (device globals: allocation-free) ----
__device__ float g_part[2 * NB][48 * 64];
__device__ float g_rsum[2 * NB][48];
__device__ unsigned int g_cnt[NB];

// ================= helpers =================
__device__ __forceinline__ u32 smem_u32(const void* p){
    u32 a; asm("{ .reg .u64 t; cvta.to.shared.u64 t, %1; cvt.u32.u64 %0, t; }" : "=r"(a) : "l"(p)); return a;
}
__device__ __forceinline__ u32 sw(u32 o){ return o ^ ((o >> 3) & 0x70); }

__device__ __forceinline__ float ex2f(float x){
    float y; asm("ex2.approx.ftz.f32 %0, %1;" : "=f"(y) : "f"(x)); return y;
}
__device__ __forceinline__ u32 bf16x2(float hi, float lo){
    u32 d; asm("cvt.rn.bf16x2.f32 %0, %1, %2;" : "=r"(d) : "f"(hi), "f"(lo)); return d;
}
__device__ __forceinline__ void ldsm4(u32& r0, u32& r1, u32& r2, u32& r3, u32 a){
    asm volatile("ldmatrix.sync.aligned.m8n8.x4.shared.b16 {%0,%1,%2,%3}, [%4];"
        : "=r"(r0), "=r"(r1), "=r"(r2), "=r"(r3) : "r"(a));
}
__device__ __forceinline__ void ldsm4t(u32& r0, u32& r1, u32& r2, u32& r3, u32 a){
    asm volatile("ldmatrix.sync.aligned.m8n8.x4.trans.shared.b16 {%0,%1,%2,%3}, [%4];"
        : "=r"(r0), "=r"(r1), "=r"(r2), "=r"(r3) : "r"(a));
}
__device__ __forceinline__ void mma_bf16(float* d, const u32* a, u32 b0, u32 b1){
    asm volatile("mma.sync.aligned.m16n8k16.row.col.f32.bf16.bf16.f32 "
        "{%0,%1,%2,%3}, {%4,%5,%6,%7}, {%8,%9}, {%0,%1,%2,%3};"
        : "+f"(d[0]), "+f"(d[1]), "+f"(d[2]), "+f"(d[3])
        : "r"(a[0]), "r"(a[1]), "r"(a[2]), "r"(a[3]), "r"(b0), "r"(b1));
}
// ---- packed f32x2 ----
__device__ __forceinline__ u64 ffma2(u64 a, u64 b, u64 c){
    u64 d; asm("fma.rn.f32x2 %0, %1, %2, %3;" : "=l"(d) : "l"(a), "l"(b), "l"(c)); return d;
}
__device__ __forceinline__ u64 pack2(float x, float y){
    u64 d; asm("mov.b64 %0, {%1, %2};" : "=l"(d) : "f"(x), "f"(y)); return d;
}
__device__ __forceinline__ float2 unpack2(u64 a){
    float2 f; asm("mov.b64 {%0, %1}, %2;" : "=f"(f.x), "=f"(f.y) : "l"(a)); return f;
}

__global__ void __launch_bounds__(NTHREADS, 2)
m2f_mma_kernel(const float* __restrict__ x, const float* __restrict__ z,
               const float* __restrict__ Wq, const float* __restrict__ bq,
               const float* __restrict__ Wo, const float* __restrict__ bo,
               float* __restrict__ out)
{
    extern __shared__ char sm[];
    float* sm_f = (float*)sm;

    const int bid  = blockIdx.x;
    const int b    = bid >> 1;         // batch
    const int half = bid & 1;          // HW-split half
    const int t0   = half * 25;        // tile range start
    const int cnt  = 25 - half;        // 25 or 24 tiles
    const int tid  = threadIdx.x;
    const int wid  = tid >> 5;
    const int lane = tid & 31;
    const int mt   = wid & 3;          // m-tile (16 q-rows)
    const int nh   = wid >> 2;         // n-half (32 cols)
    const u32 smb  = smem_u32(sm);

    const float* xb = x + (size_t)b * 64 * HW_DIM;

    // ---------------- stage z ---------------------------------------------------
    float* zs = sm_f + SM_ZS / 4;
    {
        const float* zb = z + (size_t)b * (M_DIM * D_DIM);
        for (int i = tid; i < M_DIM * D_DIM; i += NTHREADS) zs[i] = zb[i];
    }
    __syncthreads();

    // ---------------- q projection -> qs[64][64] f32 (rows 48-63 zero) -----------
    float* qs = sm_f + SM_QS / 4;
    {
        const int j0 = tid * 2;
        float ax[M_DIM], ay[M_DIM];
        const float b0 = bq[j0], b1 = bq[j0 + 1];
        #pragma unroll
        for (int m = 0; m < M_DIM; m++){ ax[m] = b0; ay[m] = b1; }
        #pragma unroll 4
        for (int k = 0; k < D_DIM; k++){
            float2 w = *(const float2*)(Wq + (size_t)k * INNER + j0);
            #pragma unroll
            for (int m = 0; m < M_DIM; m++){
                float zv = zs[m * D_DIM + k];
                ax[m] = fmaf(zv, w.x, ax[m]);
                ay[m] = fmaf(zv, w.y, ay[m]);
            }
        }
        const float scale = 0.18033688011112042f;   // 64^-0.5 * log2(e) -> ex2 softmax
        #pragma unroll
        for (int m = 0; m < M_DIM; m++){
            int f0 = m * INNER + j0;                // flat [6,512] == flat [48,64]
            int r_ = f0 >> 6, c_ = f0 & 63;
            qs[r_ * 64 + c_]     = ax[m] * scale;
            qs[r_ * 64 + c_ + 1] = ay[m] * scale;
        }
        for (int i = tid; i < 16 * 64; i += NTHREADS) qs[48 * 64 + i] = 0.f;
    }
    __syncthreads();

    // ---------------- Q -> persistent bf16 A fragments ---------------------------
    u32 aq[4][4];
    {
        int r  = 16 * mt + (lane >> 2);
        int c  = (lane & 3) * 2;
        #pragma unroll
        for (int ks = 0; ks < 4; ks++){
            float2 v0 = *(const float2*)(qs + r * 64        + 16 * ks + c);
            float2 v1 = *(const float2*)(qs + (r + 8) * 64  + 16 * ks + c);
            float2 v2 = *(const float2*)(qs + r * 64        + 16 * ks + c + 8);
            float2 v3 = *(const float2*)(qs + (r + 8) * 64  + 16 * ks + c + 8);
            aq[ks][0] = bf16x2(v0.y, v0.x);
            aq[ks][1] = bf16x2(v1.y, v1.x);
            aq[ks][2] = bf16x2(v2.y, v2.x);
            aq[ks][3] = bf16x2(v3.y, v3.x);
        }
    }

    // ---------------- X tile load helpers ---------------------------------------
    const int cc = tid >> 2, ng = tid & 3;
    const float* xrow = xb + (size_t)cc * HW_DIM + ng * 16;
    float4 v[4];

    auto ldg_tile = [&](int t){
        const float* src = xrow + 64 * t;
        #pragma unroll
        for (int i = 0; i < 4; i++) v[i] = *(const float4*)(src + 4 * i);
    };
    auto sts_tile = [&](int buf){
        char* dst = sm + SM_X + buf * 8192;
        uint4 p0, p1;
        p0.x = bf16x2(v[0].y, v[0].x); p0.y = bf16x2(v[0].w, v[0].z);
        p0.z = bf16x2(v[1].y, v[1].x); p0.w = bf16x2(v[1].w, v[1].z);
        p1.x = bf16x2(v[2].y, v[2].x); p1.y = bf16x2(v[2].w, v[2].z);
        p1.z = bf16x2(v[3].y, v[3].x); p1.w = bf16x2(v[3].w, v[3].z);
        u32 base = (u32)(cc * 128 + ng * 32);
        *(uint4*)(dst + sw(base))      = p0;
        *(uint4*)(dst + sw(base + 16)) = p1;
    };

    ldg_tile(t0); sts_tile(0);
    ldg_tile(t0 + 1);
    __syncthreads();

    // ---------------- per-thread invariant ldmatrix address parts ----------------
    const u32 smP = smb + SM_P;
    const int lrow = ((lane >> 3) & 1) * 8 + (lane & 7);
    const u32 g1chunk = (u32)(4 * nh + (lane >> 4));
    const u32 g2arow  = (u32)(16 * mt + lrow);
    const u32 g2brow  = (u32)(32 * nh + (lane >> 4) * 8 + (lane & 7));
    const u32 g2bch   = (u32)((lane >> 3) & 1);

    const int rA = 16 * mt + (lane >> 2);
    const int rB = rA + 8;
    const int cB = 32 * nh + (lane & 3) * 2;

    float o[4][4];
    #pragma unroll
    for (int i = 0; i < 4; i++)
        #pragma unroll
        for (int j = 0; j < 4; j++) o[i][j] = 0.f;
    float racc0 = 0.f, racc1 = 0.f;

    // ---------------- main loop over this half's tiles ---------------------------
    for (int i = 0; i < cnt; i++){
        const u32 XS = smb + SM_X + (u32)(i & 1) * 8192;

        // GEMM1: S = Q . Xtile   (k = c)
        float s[4][4];
        #pragma unroll
        for (int a_ = 0; a_ < 4; a_++)
            #pragma unroll
            for (int j = 0; j < 4; j++) s[a_][j] = 0.f;
        #pragma unroll
        for (int ks = 0; ks < 4; ks++){
            #pragma unroll
            for (int np = 0; np < 2; np++){
                u32 b0, b1, b2, b3;
                u32 ad = XS + sw((u32)((16 * ks + lrow) * 128) + (g1chunk + 2 * np) * 16);
                ldsm4t(b0, b1, b2, b3, ad);
                mma_bf16(s[2 * np],     aq[ks], b0, b1);
                mma_bf16(s[2 * np + 1], aq[ks], b2, b3);
            }
        }

        // exp + rowsum + pack P to smem bf16
        #pragma unroll
        for (int nt = 0; nt < 4; nt++){
            float e0 = ex2f(s[nt][0]), e1 = ex2f(s[nt][1]);
            float e2 = ex2f(s[nt][2]), e3 = ex2f(s[nt][3]);
            racc0 += e0 + e1;
            racc1 += e2 + e3;
            u32 colb = (u32)((cB + 8 * nt) * 2);
            *(u32*)(sm + SM_P + sw((u32)(rA * 128) + colb)) = bf16x2(e1, e0);
            *(u32*)(sm + SM_P + sw((u32)(rB * 128) + colb)) = bf16x2(e3, e2);
        }
        __syncthreads();   // P complete

        // GEMM2: O += P . X^T   (k = n)
        #pragma unroll
        for (int ks = 0; ks < 4; ks++){
            u32 a0, a1, a2, a3;
            u32 ad = smP + sw(g2arow * 128 + (u32)(2 * ks + (lane >> 4)) * 16);
            ldsm4(a0, a1, a2, a3, ad);
            u32 ap[4] = {a0, a1, a2, a3};
            #pragma unroll
            for (int cp = 0; cp < 2; cp++){
                u32 b0, b1, b2, b3;
                u32 bd = XS + sw((g2brow + 16 * cp) * 128 + (u32)(2 * ks) * 16 + g2bch * 16);
                ldsm4(b0, b1, b2, b3, bd);
                mma_bf16(o[2 * cp],     ap, b0, b1);
                mma_bf16(o[2 * cp + 1], ap, b2, b3);
            }
        }

        // stage next tiles
        if (i + 1 < cnt) sts_tile((i + 1) & 1);
        if (i + 2 < cnt) ldg_tile(t0 + i + 2);
        __syncthreads();   // next X ready; P consumed
    }

    // ---------------- rowsum reduce ---------------------------------------------
    racc0 += __shfl_xor_sync(0xffffffffu, racc0, 1);
    racc0 += __shfl_xor_sync(0xffffffffu, racc0, 2);
    racc1 += __shfl_xor_sync(0xffffffffu, racc1, 1);
    racc1 += __shfl_xor_sync(0xffffffffu, racc1, 2);
    float* rex = sm_f + SM_REX / 4;
    if ((lane & 3) == 0){
        rex[wid * 16 + (lane >> 2)]     = racc0;
        rex[wid * 16 + (lane >> 2) + 8] = racc1;
    }
    __syncthreads();

    // ---------------- write partial O + rowsum to global scratch -----------------
    #pragma unroll
    for (int nt = 0; nt < 4; nt++){
        int c = cB + 8 * nt;
        if (rA < 48){
            g_part[bid][rA * 64 + c]     = o[nt][0];
            g_part[bid][rA * 64 + c + 1] = o[nt][1];
        }
        if (rB < 48){
            g_part[bid][rB * 64 + c]     = o[nt][2];
            g_part[bid][rB * 64 + c + 1] = o[nt][3];
        }
    }
    if (tid < 48)
        g_rsum[bid][tid] = rex[(tid >> 4) * 16 + (tid & 15)]
                         + rex[((tid >> 4) + 4) * 16 + (tid & 15)];
    __threadfence();
    __syncthreads();

    // ---------------- pair rendezvous: last CTA combines -------------------------
    float* flag = sm_f + SM_ZS / 4;
    if (tid == 0){
        unsigned int old = atomicAdd(&g_cnt[b], 1);
        flag[0] = (float)old;
    }
    __syncthreads();
    if (flag[0] == 0.f) return;          // first-arriving CTA exits

    if (tid == 0) g_cnt[b] = 0;          // reset for next graph replay

    // per-row inverse sums (fixed order: half0 + half1 -> deterministic)
    if (tid < 48)
        rex[tid] = 1.0f / (g_rsum[2 * b][tid] + g_rsum[2 * b + 1][tid]);
    __syncthreads();

    // combine partials -> resm [hc=512][m-pairs(8)]
    float* resm = sm_f + SM_RESM / 4;
    for (int i = tid; i < 48 * 64; i += NTHREADS){
        int r = i >> 6, c = i & 63;
        float val = (g_part[2 * b][i] + g_part[2 * b + 1][i]) * rex[r];
        int h = r / 6, m = r - 6 * h;
        resm[(h * 64 + c) * 8 + m] = val;
    }
    __syncthreads();

    // ---------------- out = resT @ Wo + bo + z ----------------------------------
    if (tid < D_DIM){
        const int j = tid;
        u64 acc[3] = {0ULL, 0ULL, 0ULL};
        #pragma unroll 8
        for (int k = 0; k < INNER; k++){
            float w = Wo[(size_t)k * D_DIM + j];
            u64 wd = pack2(w, w);
            const u64* rm = (const u64*)(resm + k * 8);
            #pragma unroll
            for (int p = 0; p < 3; p++)
                acc[p] = ffma2(wd, rm[p], acc[p]);
        }
        const float bj = bo[j];
        const float* zb = z   + (size_t)b * M_DIM * D_DIM;
        float*       ob = out + (size_t)b * M_DIM * D_DIM;
        #pragma unroll
        for (int p = 0; p < 3; p++){
            float2 vv = unpack2(acc[p]);
            ob[(2 * p)     * D_DIM + j] = vv.x + bj + zb[(2 * p)     * D_DIM + j];
            ob[(2 * p + 1) * D_DIM + j] = vv.y + bj + zb[(2 * p + 1) * D_DIM + j];
        }
    }
}

extern "C" void kernel_launch(void* const* d_in, const int* in_sizes, int n_in,
                              void* d_out, int out_size)
{
    const float* x  = (const float*)d_in[0];
    const float* z  = (const float*)d_in[1];
    const float* Wq = (const float*)d_in[2];
    const float* bq = (const float*)d_in[3];
    const float* Wo = (const float*)d_in[4];
    const float* bo = (const float*)d_in[5];
    float* out = (float*)d_out;

    cudaFuncSetAttribute(m2f_mma_kernel, cudaFuncAttributeMaxDynamicSharedMemorySize, SM_TOTAL);
    m2f_mma_kernel<<<2 * NB, NTHREADS, SM_TOTAL>>>(x, z, Wq, bq, Wo, bo, out);
}